// round 10
// baseline (speedup 1.0000x reference)
#include <cuda_runtime.h>
#include <math.h>

#define PI_F 3.14159265358979323846f

static constexpr int NA = 4096;
static constexpr int NP = 49152;
static constexpr float RCUT = 5.0f;

// ---------- setup tables ----------
__device__ float g_Y[512 * 25];
__device__ float g_w[512];
__device__ float g_G[5625];
__device__ int   g_tds[10];
__device__ int   g_tdp[768];
__device__ float g_tdv[768];
// (j,k)-grouped Gaunt list for attention: entries (i, val) for each cell jk = j*25+k
__device__ int   g_gjs[226];
__device__ int   g_gi[5664];
__device__ float g_gv[5664];

// ---------- CSR by destination atom ----------
__device__ int g_cnt[4096];
__device__ int g_rowstart[4097];
__device__ int g_fillptr[4096];
__device__ int g_plist[NP];
__device__ int g_dstpos[NP];
// ---------- CSR by source atom ----------
__device__ int g_cntS[4096];
__device__ int g_rsS[4097];
__device__ int g_fpS[4096];
__device__ int g_slist[NP];

// ---------- per-pair / per-atom data ----------
__device__ float g_sh[NP * 9];
__device__ float g_rb[NP * 16];
__device__ float g_pairy[NP * 144];
__device__ float g_x0[NA * 400];
__device__ float g_x1[NA * 400];
__device__ float g_xq[NA * 400];
__device__ float g_xk[NA * 400];
__device__ float g_xv[NA * 400];
__device__ float g_vf[(size_t)NP * 400];
__device__ float g_sv[NP];

__constant__ float GLX[16] = {
    -0.98940093499164993f, -0.94457502307323258f, -0.86563120238783174f, -0.75540440835500303f,
    -0.61787624440264375f, -0.45801677765722739f, -0.28160355077925891f, -0.09501250983763744f,
     0.09501250983763744f,  0.28160355077925891f,  0.45801677765722739f,  0.61787624440264375f,
     0.75540440835500303f,  0.86563120238783174f,  0.94457502307323258f,  0.98940093499164993f };
__constant__ float GLW[16] = {
    0.02715245941175409f, 0.06225352393864789f, 0.09515851168249278f, 0.12462897125553387f,
    0.14959598881657673f, 0.16915651939500254f, 0.18260341504492359f, 0.18945061045506850f,
    0.18945061045506850f, 0.18260341504492359f, 0.16915651939500254f, 0.14959598881657673f,
    0.12462897125553387f, 0.09515851168249278f, 0.06225352393864789f, 0.02715245941175409f };

__device__ __forceinline__ float shfl16(float v, int s) {
    return __shfl_sync(0xffffffffu, v, s, 16);
}
__device__ __forceinline__ int deg25(int l) {
    return (l < 1) ? 0 : ((l < 4) ? 1 : ((l < 9) ? 2 : ((l < 16) ? 3 : 4)));
}
__device__ __forceinline__ float factf(int n) {
    float r = 1.f;
    for (int i = 2; i <= n; i++) r *= (float)i;
    return r;
}
__device__ __forceinline__ int warp_excl_scan(int v) {
    int x = v;
#pragma unroll
    for (int d = 1; d < 32; d <<= 1) {
        int y = __shfl_up_sync(0xffffffffu, x, d);
        if ((int)(threadIdx.x & 31) >= d) x += y;
    }
    return x - v;
}

template <int LM>
__device__ __forceinline__ void rsph(float x, float y, float z, float* out) {
    float phi = atan2f(y, x);
    float ct = fminf(fmaxf(z, -1.f), 1.f);
    float st = sqrtf(fmaxf(1.f - ct * ct, 0.f));
    float P[LM + 1][LM + 1];
    P[0][0] = 1.f;
#pragma unroll
    for (int m = 1; m <= LM; m++) P[m][m] = -(2.f * m - 1.f) * st * P[m - 1][m - 1];
#pragma unroll
    for (int m = 0; m < LM; m++) P[m + 1][m] = (2.f * m + 1.f) * ct * P[m][m];
#pragma unroll
    for (int m = 0; m <= LM; m++) {
#pragma unroll
        for (int l = m + 2; l <= LM; l++)
            P[l][m] = ((2.f * l - 1.f) * ct * P[l - 1][m] - (float)(l + m - 1) * P[l - 2][m]) / (float)(l - m);
    }
    int idx = 0;
#pragma unroll
    for (int l = 0; l <= LM; l++) {
#pragma unroll
        for (int mm = -l; mm <= l; mm++) {
            int ma = mm < 0 ? -mm : mm;
            float Nn = sqrtf((2.f * l + 1.f) / (4.f * PI_F) * factf(l - ma) / factf(l + ma));
            float cs = (ma & 1) ? -1.f : 1.f;
            float Yv;
            if (mm == 0)      Yv = Nn * P[l][0];
            else if (mm > 0)  Yv = 1.41421356237309515f * Nn * cs * cosf((float)mm * phi) * P[l][ma];
            else              Yv = 1.41421356237309515f * Nn * cs * sinf((float)ma * phi) * P[l][ma];
            out[idx++] = Yv;
        }
    }
}

// ---------- setup kernels ----------
__global__ void k_quad_Y() {
    int t = blockIdx.x * blockDim.x + threadIdx.x;
    if (t < 512) {
        int it = t >> 5, ip = t & 31;
        float ct = GLX[it];
        float ph = (float)ip * (2.f * PI_F / 32.f);
        float st = sqrtf(fmaxf(1.f - ct * ct, 0.f));
        float Yv[25];
        rsph<4>(st * cosf(ph), st * sinf(ph), ct, Yv);
#pragma unroll
        for (int i = 0; i < 25; i++) g_Y[t * 25 + i] = Yv[i];
        g_w[t] = GLW[it] * (2.f * PI_F / 32.f);
    } else if (t < 512 + 4096) {
        g_cnt[t - 512] = 0;
    } else if (t < 512 + 8192) {
        g_cntS[t - 512 - 4096] = 0;
    }
}

__global__ void k_quad_G() {
    int t = blockIdx.x * blockDim.x + threadIdx.x;
    if (t >= 5625) return;
    int i = t / 225, rem = t % 225;
    int j = rem / 25, k = rem % 25;
    float acc = 0.f;
#pragma unroll 4
    for (int g = 0; g < 512; g++)
        acc += g_w[g] * g_Y[g * 25 + i] * g_Y[g * 25 + j] * g_Y[g * 25 + k];
    g_G[t] = (fabsf(acc) < 1e-6f) ? 0.f : acc;
}

__global__ void k_build_lists() {
    __shared__ float sG[5625];
    __shared__ int sCnt[256];
    int tid = threadIdx.x;
    for (int t = tid; t < 5625; t += 256) sG[t] = g_G[t];
    __syncthreads();
    // ---- (j,k)-grouped Gaunt list ----
    int c = 0;
    if (tid < 225) {
        int j = tid / 25, k = tid % 25;
        for (int i = 0; i < 25; i++)
            if (sG[i * 225 + j * 25 + k] != 0.f) c++;
    }
    sCnt[tid] = c;
    __syncthreads();
    for (int off = 1; off < 256; off <<= 1) {
        int v = (tid >= off) ? sCnt[tid - off] : 0;
        __syncthreads();
        sCnt[tid] += v;
        __syncthreads();
    }
    int start = sCnt[tid] - c;
    if (tid < 225) {
        g_gjs[tid] = start;
        int j = tid / 25, k = tid % 25;
        int o = start;
        for (int i = 0; i < 25; i++) {
            float v = sG[i * 225 + j * 25 + k];
            if (v != 0.f) { g_gi[o] = i; g_gv[o] = v; o++; }
        }
        if (tid == 224) g_gjs[225] = o;
    }
    __syncthreads();
    // ---- TD list grouped by output k (first warp) ----
    if (tid >= 32) return;
    int lane = tid;
    int cntT = 0;
    if (lane < 9) {
        for (int i = 0; i < 9; i++)
            for (int j = 0; j < 9; j++)
                if (sG[i * 225 + j * 25 + lane] != 0.f) cntT++;
    }
    int offT = warp_excl_scan(cntT);
    if (lane < 9) g_tds[lane] = offT;
    if (lane == 8) g_tds[9] = offT + cntT;
    if (lane < 9) {
        int o = offT;
        for (int i = 0; i < 9; i++)
            for (int j = 0; j < 9; j++) {
                float v = sG[i * 225 + j * 25 + lane];
                if (v != 0.f) {
                    int di = (i < 1) ? 0 : (i < 4) ? 1 : 2;
                    int dj = (j < 1) ? 0 : (j < 4) ? 1 : 2;
                    g_tdp[o] = (di * 3 + dj) | (i << 8) | (j << 16);
                    g_tdv[o] = v;
                    o++;
                }
            }
    }
}

// ---------- CSR build (generic over dst/src column) ----------
__global__ void k_hist(const int* __restrict__ nbr, int col, int* __restrict__ cnt) {
    int p = blockIdx.x * blockDim.x + threadIdx.x;
    if (p < NP) atomicAdd(&cnt[nbr[2 * p + col]], 1);
}
__global__ void k_scan(const int* __restrict__ cnt, int* __restrict__ rowstart,
                       int* __restrict__ fillptr) {
    __shared__ int s[1024];
    int t = threadIdx.x;
    int c[4], tot = 0;
#pragma unroll
    for (int i = 0; i < 4; i++) { c[i] = cnt[t * 4 + i]; tot += c[i]; }
    s[t] = tot; __syncthreads();
    for (int off = 1; off < 1024; off <<= 1) {
        int v = (t >= off) ? s[t - off] : 0;
        __syncthreads();
        s[t] += v;
        __syncthreads();
    }
    int base = s[t] - tot;
#pragma unroll
    for (int i = 0; i < 4; i++) {
        rowstart[t * 4 + i] = base;
        fillptr[t * 4 + i] = base;
        base += c[i];
    }
    if (t == 1023) rowstart[4096] = base;
}
__global__ void k_fill_dst(const int* __restrict__ nbr) {
    int p = blockIdx.x * blockDim.x + threadIdx.x;
    if (p >= NP) return;
    int pos = atomicAdd(&g_fillptr[nbr[2 * p]], 1);
    g_plist[pos] = p;
    g_dstpos[p] = pos;
}
__global__ void k_fill_src(const int* __restrict__ nbr) {
    int p = blockIdx.x * blockDim.x + threadIdx.x;
    if (p >= NP) return;
    int pos = atomicAdd(&g_fpS[nbr[2 * p + 1]], 1);
    g_slist[pos] = p;
}

// ---------- pair tensor-product message pass ----------
__global__ void k_pair_td(const int* __restrict__ nbr, const float* __restrict__ disp,
                          const int* __restrict__ Z, const float* __restrict__ W_rad,
                          const float* __restrict__ W1, const float* __restrict__ W2,
                          const float* __restrict__ W3) {
    __shared__ float sW1[768], sW2[768], sW3[768];
    __shared__ float sC[16][81];
    __shared__ float sSh[16][9];
    __shared__ int   sTds[10];
    __shared__ int   sTdp[768];
    __shared__ float sTdv[768];
    int tid = threadIdx.x;
    for (int t = tid; t < 768; t += 256) { sW1[t] = W1[t]; sW2[t] = W2[t]; sW3[t] = W3[t]; }
    if (tid < 10) sTds[tid] = g_tds[tid];
    int nT = g_tds[9];
    for (int t = tid; t < nT; t += 256) { sTdp[t] = g_tdp[t]; sTdv[t] = g_tdv[t]; }
    int pl = tid >> 4, lane = tid & 15;
    int p = blockIdx.x * 16 + pl;
    int src = nbr[2 * p + 1];
    float dx = disp[3 * p], dy = disp[3 * p + 1], dz = disp[3 * p + 2];
    float r = sqrtf(dx * dx + dy * dy + dz * dz);
    float inv = 1.f / fmaxf(r, 1e-9f);
    float sh[9];
    rsph<2>(dx * inv, dy * inv, dz * inv, sh);
    if (lane == 0) {
#pragma unroll
        for (int i = 0; i < 9; i++) { sSh[pl][i] = sh[i]; g_sh[p * 9 + i] = sh[i]; }
    }
    float xk = (float)(lane + 1) * r * (1.f / RCUT);
    float px = PI_F * xk;
    float rb = (px > 0.f) ? (sinf(px) / px) : 1.f;
    if (r >= RCUT) rb = 0.f;
    g_rb[p * 16 + lane] = rb;
    __syncthreads();
    float y0 = 0.f;
    const float* wr = W_rad + Z[src] * 256;
#pragma unroll
    for (int k2 = 0; k2 < 16; k2++) y0 += shfl16(rb, k2) * wr[k2 * 16 + lane];
    float A0 = 0, A1 = 0, A2 = 0, B0 = 0, B1 = 0, B2 = 0;
#pragma unroll
    for (int f = 0; f < 16; f++) {
        float yv = shfl16(y0, f);
        A0 += yv * sW1[0 * 256 + f * 16 + lane];
        A1 += yv * sW1[1 * 256 + f * 16 + lane];
        A2 += yv * sW1[2 * 256 + f * 16 + lane];
        B0 += yv * sW2[0 * 256 + f * 16 + lane];
        B1 += yv * sW2[1 * 256 + f * 16 + lane];
        B2 += yv * sW2[2 * 256 + f * 16 + lane];
    }
    float P9[9];
    P9[0] = A0 * B0; P9[1] = A0 * B1; P9[2] = A0 * B2;
    P9[3] = A1 * B0; P9[4] = A1 * B1; P9[5] = A1 * B2;
    P9[6] = A2 * B0; P9[7] = A2 * B1; P9[8] = A2 * B2;
    for (int t = lane; t < 81; t += 16) sC[pl][t] = 0.f;
    __syncwarp(0xffffffffu);
    if (lane < 9) {
        int e0 = sTds[lane], e1 = sTds[lane + 1];
        for (int e = e0; e < e1; e++) {
            int pk = sTdp[e];
            sC[pl][lane * 9 + (pk & 255)] += sTdv[e] * sSh[pl][(pk >> 8) & 255] * sSh[pl][pk >> 16];
        }
    }
    __syncwarp(0xffffffffu);
    float tp[9];
#pragma unroll
    for (int k = 0; k < 9; k++) {
        float acc = 0.f;
#pragma unroll
        for (int dd = 0; dd < 9; dd++) acc += sC[pl][k * 9 + dd] * P9[dd];
        tp[k] = acc;
    }
#pragma unroll
    for (int k = 0; k < 9; k++) {
        int dk = (k < 1) ? 0 : (k < 4) ? 1 : 2;
        float acc = 0.f;
#pragma unroll
        for (int f = 0; f < 16; f++)
            acc += shfl16(tp[k], f) * sW3[dk * 256 + f * 16 + lane];
        g_pairy[p * 144 + k * 16 + lane] = acc;
    }
}

// ---------- per-atom mean (dst-CSR gather) ----------
__global__ void k_mp_gather() {
    int tid = threadIdx.x, a = blockIdx.x;
    int b0 = g_rowstart[a], deg = g_rowstart[a + 1] - b0;
    float a0 = 0.f, a1 = 0.f;
    for (int i = 0; i < deg; i++) {
        const float* py = g_pairy + (size_t)g_plist[b0 + i] * 144;
        a0 += py[tid];
        if (tid < 16) a1 += py[tid + 128];
    }
    float inv = 1.f / fmaxf((float)deg, 1.f);
    g_x0[a * 400 + tid] = a0 * inv;
    g_x0[a * 400 + 128 + tid] = (tid < 16) ? a1 * inv : 0.f;
    g_x0[a * 400 + 256 + tid] = 0.f;
    if (tid < 16) g_x0[a * 400 + 384 + tid] = 0.f;
}

// ---------- per-atom q/k/v projections ----------
__global__ void k_qkv(const float* __restrict__ x, const float* __restrict__ Wq,
                      const float* __restrict__ Wk, const float* __restrict__ Wv) {
    __shared__ float sq[1280], sk[1280], sv[1280];
    int tid = threadIdx.x;
    for (int t = tid; t < 1280; t += 256) { sq[t] = Wq[t]; sk[t] = Wk[t]; sv[t] = Wv[t]; }
    __syncthreads();
    int unit = tid >> 4, lane = tid & 15;
    for (int g = 0; g < 8; g++) {
        int gu = blockIdx.x * 128 + g * 16 + unit;
        int row = gu % 25;
        int d = deg25(row);
        float xv = x[gu * 16 + lane];
        float aq = 0, ak = 0, av = 0;
#pragma unroll
        for (int f = 0; f < 16; f++) {
            float xs = shfl16(xv, f);
            aq += xs * sq[d * 256 + f * 16 + lane];
            ak += xs * sk[d * 256 + f * 16 + lane];
            av += xs * sv[d * 256 + f * 16 + lane];
        }
        g_xq[gu * 16 + lane] = aq;
        g_xk[gu * 16 + lane] = ak;
        g_xv[gu * 16 + lane] = av;
    }
}

// ---------- attention, src-grouped: U[j,k,f] once per src atom, dense j-loop per pair ----------
__global__ void __launch_bounds__(256) k_att_src(const int* __restrict__ nbr,
                                                 const float* __restrict__ Wb) {
    __shared__ float4 sU[9][25][8];   // {Uk_f0, Uk_f1, Uv_f0, Uv_f1}
    __shared__ float4 sX[25][8];      // {xk_f0, xk_f1, xv_f0, xv_f1}
    __shared__ float  sWb[256];
    __shared__ float  sSh[9];
    __shared__ float  sWf[16];
    __shared__ float  sRed[8];
    int a = blockIdx.x, t = threadIdx.x;
    int b0 = g_rsS[a], deg = g_rsS[a + 1] - b0;
    if (deg == 0) return;
    sWb[t] = Wb[t];
    // stage this src atom's k/v features
    if (t < 200) {
        int i = t >> 3, fp = t & 7;
        float2 kk = *(const float2*)&g_xk[a * 400 + i * 16 + 2 * fp];
        float2 vv = *(const float2*)&g_xv[a * 400 + i * 16 + 2 * fp];
        sX[i][fp] = make_float4(kk.x, kk.y, vv.x, vv.y);
    }
    __syncthreads();
    // build U: slot = jk*8 + fp
    for (int slot = t; slot < 1800; slot += 256) {
        int jk = slot >> 3, fp = slot & 7;
        int e0 = g_gjs[jk], e1 = g_gjs[jk + 1];
        float4 acc = make_float4(0.f, 0.f, 0.f, 0.f);
        for (int e = e0; e < e1; e++) {
            float gv = g_gv[e];
            float4 x = sX[g_gi[e]][fp];
            acc.x += gv * x.x; acc.y += gv * x.y;
            acc.z += gv * x.z; acc.w += gv * x.w;
        }
        sU[jk / 25][jk % 25][fp] = acc;
    }
    __syncthreads();
    int kk_ = t >> 3, fp = t & 7;     // valid for t < 200
    int warp = t >> 5, lane = t & 31;
    for (int n = 0; n < deg; n++) {
        int p = g_slist[b0 + n];
        int dst = nbr[2 * p];
        int pos = g_dstpos[p];
        if (t < 9) sSh[t] = g_sh[p * 9 + t];
        if (t < 16) {
            float acc = 0.f;
#pragma unroll
            for (int k2 = 0; k2 < 16; k2++) acc += g_rb[p * 16 + k2] * sWb[k2 * 16 + t];
            sWf[t] = acc;
        }
        __syncthreads();
        float s_part = 0.f;
        if (t < 200) {
            float2 q = *(const float2*)&g_xq[dst * 400 + kk_ * 16 + 2 * fp];
            float akx = 0.f, aky = 0.f, avz = 0.f, avw = 0.f;
#pragma unroll
            for (int j = 0; j < 9; j++) {
                float shv = sSh[j];
                float4 u = sU[j][kk_][fp];
                akx += shv * u.x; aky += shv * u.y;
                avz += shv * u.z; avw += shv * u.w;
            }
            float wf0 = sWf[2 * fp], wf1 = sWf[2 * fp + 1];
            *(float2*)&g_vf[(size_t)pos * 400 + kk_ * 16 + 2 * fp] =
                make_float2(wf0 * avz, wf1 * avw);
            s_part = q.x * wf0 * akx + q.y * wf1 * aky;
        }
#pragma unroll
        for (int d = 16; d >= 1; d >>= 1)
            s_part += __shfl_down_sync(0xffffffffu, s_part, d, 32);
        if (lane == 0) sRed[warp] = s_part;
        __syncthreads();
        if (t == 0) {
            float sv = 0.f;
#pragma unroll
            for (int w = 0; w < 8; w++) sv += sRed[w];
            g_sv[pos] = sv * 0.05f;
        }
    }
}

// ---------- fused softmax + aggregation + output projection (contiguous CSR) ----------
__global__ void __launch_bounds__(128) k_att_out(const float* __restrict__ Wo,
                                                 const float* __restrict__ bo,
                                                 float* __restrict__ xout) {
    __shared__ float sWo[1280];
    __shared__ float sb[16];
    __shared__ float sAgg[400];
    __shared__ float red[128];
    int tid = threadIdx.x, a = blockIdx.x;
    for (int t = tid; t < 1280; t += 128) sWo[t] = Wo[t];
    if (tid < 16) sb[tid] = bo[tid];
    int b0 = g_rowstart[a], deg = g_rowstart[a + 1] - b0;
    float m = -1e30f;
    for (int i = tid; i < deg; i += 128) m = fmaxf(m, g_sv[b0 + i]);
    red[tid] = m; __syncthreads();
    for (int s = 64; s > 0; s >>= 1) { if (tid < s) red[tid] = fmaxf(red[tid], red[tid + s]); __syncthreads(); }
    m = red[0]; __syncthreads();
    float d = 0.f;
    for (int i = tid; i < deg; i += 128) d += expf(g_sv[b0 + i] - m);
    red[tid] = d; __syncthreads();
    for (int s = 64; s > 0; s >>= 1) { if (tid < s) red[tid] += red[tid + s]; __syncthreads(); }
    float invden = 1.f / (red[0] + 1e-9f);
    __syncthreads();
    if (tid < 100) {
        float4 acc = make_float4(0.f, 0.f, 0.f, 0.f);
        for (int i = 0; i < deg; i++) {
            float al = expf(g_sv[b0 + i] - m) * invden;
            float4 vv = *(const float4*)(g_vf + (size_t)(b0 + i) * 400 + tid * 4);
            acc.x += al * vv.x; acc.y += al * vv.y;
            acc.z += al * vv.z; acc.w += al * vv.w;
        }
        *(float4*)&sAgg[tid * 4] = acc;
    }
    __syncthreads();
    for (int idx = tid; idx < 400; idx += 128) {
        int row = idx >> 4, g = idx & 15, dg = deg25(row);
        const float* w = &sWo[dg * 256];
        float acc = 0.f;
#pragma unroll
        for (int f = 0; f < 16; f++) acc += sAgg[row * 16 + f] * w[f * 16 + g];
        if (row == 0) acc += sb[g];
        xout[a * 400 + idx] = acc;
    }
}

// ---------- final residual on row 0 ----------
__global__ void k_final(const int* __restrict__ Z, const float* __restrict__ emb,
                        const float* __restrict__ W_emb, const float* __restrict__ b_emb,
                        float* __restrict__ out) {
    int tid = blockIdx.x * blockDim.x + threadIdx.x;
    int atom = tid >> 4, lane = tid & 15;
    if (atom >= NA) return;
    const float* er = emb + Z[atom] * 32;
    float acc = b_emb[lane];
#pragma unroll 8
    for (int e = 0; e < 32; e++) acc += er[e] * W_emb[e * 16 + lane];
    out[atom * 400 + lane] += acc;
}

extern "C" void kernel_launch(void* const* d_in, const int* in_sizes, int n_in,
                              void* d_out, int out_size) {
    const int*   Z     = (const int*)d_in[0];
    const int*   nbr   = (const int*)d_in[1];
    const float* disp  = (const float*)d_in[2];
    const float* W_rad = (const float*)d_in[3];
    const float* emb   = (const float*)d_in[4];
    const float* W_emb = (const float*)d_in[5];
    const float* b_emb = (const float*)d_in[6];
    const float* tdW1  = (const float*)d_in[7];
    const float* tdW2  = (const float*)d_in[8];
    const float* tdW3  = (const float*)d_in[9];
    const float* Wb[2] = { (const float*)d_in[10], (const float*)d_in[16] };
    const float* Wq[2] = { (const float*)d_in[11], (const float*)d_in[17] };
    const float* Wk[2] = { (const float*)d_in[12], (const float*)d_in[18] };
    const float* Wv[2] = { (const float*)d_in[13], (const float*)d_in[19] };
    const float* Wo[2] = { (const float*)d_in[14], (const float*)d_in[20] };
    const float* bo[2] = { (const float*)d_in[15], (const float*)d_in[21] };
    float* out = (float*)d_out;

    float *x0p, *x1p;
    cudaGetSymbolAddress((void**)&x0p, g_x0);
    cudaGetSymbolAddress((void**)&x1p, g_x1);
    int *cntD, *rsD, *fpD, *cntS, *rsS, *fpS;
    cudaGetSymbolAddress((void**)&cntD, g_cnt);
    cudaGetSymbolAddress((void**)&rsD, g_rowstart);
    cudaGetSymbolAddress((void**)&fpD, g_fillptr);
    cudaGetSymbolAddress((void**)&cntS, g_cntS);
    cudaGetSymbolAddress((void**)&rsS, g_rsS);
    cudaGetSymbolAddress((void**)&fpS, g_fpS);

    k_quad_Y<<<34, 256>>>();
    k_quad_G<<<45, 128>>>();
    k_build_lists<<<1, 256>>>();
    k_pair_td<<<NP / 16, 256>>>(nbr, disp, Z, W_rad, tdW1, tdW2, tdW3);  // 4th -> ncu
    k_hist<<<NP / 256, 256>>>(nbr, 0, cntD);
    k_hist<<<NP / 256, 256>>>(nbr, 1, cntS);
    k_scan<<<1, 1024>>>(cntD, rsD, fpD);
    k_scan<<<1, 1024>>>(cntS, rsS, fpS);
    k_fill_dst<<<NP / 256, 256>>>(nbr);
    k_fill_src<<<NP / 256, 256>>>(nbr);
    k_mp_gather<<<NA, 128>>>();

    for (int L = 0; L < 2; L++) {
        const float* xi = (L == 0) ? x0p : x1p;
        float* xo = (L == 0) ? x1p : out;
        k_qkv<<<NA * 25 / 128, 256>>>(xi, Wq[L], Wk[L], Wv[L]);
        k_att_src<<<NA, 256>>>(nbr, Wb[L]);
        k_att_out<<<NA, 128>>>(Wo[L], bo[L], xo);
    }
    k_final<<<256, 256>>>(Z, emb, W_emb, b_emb, out);
}

// round 13
// speedup vs baseline: 1.0821x; 1.0821x over previous
#include <cuda_runtime.h>
#include <math.h>

#define PI_F 3.14159265358979323846f

static constexpr int NA = 4096;
static constexpr int NP = 49152;
static constexpr float RCUT = 5.0f;

// ---------- setup tables ----------
__device__ float g_Y[512 * 25];
__device__ float g_w[512];
__device__ float g_G[5625];
__device__ int   g_hk[26];
__device__ int   g_hi[640];
__device__ int   g_hjs[648];
__device__ int   g_lj[5664];
__device__ float g_lv[5664];
__device__ int   g_tds[10];
__device__ int   g_tdp[768];
__device__ float g_tdv[768];
__device__ int   g_ks4[5];

// ---------- CSR by destination atom ----------
__device__ int g_cnt[4096];
__device__ int g_rowstart[4097];
__device__ int g_fillptr[4096];
__device__ int g_plist[NP];
__device__ int g_dstpos[NP];

// ---------- per-pair / per-atom data (pair arrays in CSR order) ----------
__device__ float g_sh[NP * 9];
__device__ float g_rb[NP * 16];
__device__ float g_pairy[NP * 144];
__device__ float g_x0[NA * 400];
__device__ float g_x1[NA * 400];
__device__ float g_xq[NA * 400];
__device__ float g_xk[NA * 400];
__device__ float g_xv[NA * 400];
__device__ float g_vf[(size_t)NP * 400];
__device__ float g_sv[NP];

__constant__ float GLX[16] = {
    -0.98940093499164993f, -0.94457502307323258f, -0.86563120238783174f, -0.75540440835500303f,
    -0.61787624440264375f, -0.45801677765722739f, -0.28160355077925891f, -0.09501250983763744f,
     0.09501250983763744f,  0.28160355077925891f,  0.45801677765722739f,  0.61787624440264375f,
     0.75540440835500303f,  0.86563120238783174f,  0.94457502307323258f,  0.98940093499164993f };
__constant__ float GLW[16] = {
    0.02715245941175409f, 0.06225352393864789f, 0.09515851168249278f, 0.12462897125553387f,
    0.14959598881657673f, 0.16915651939500254f, 0.18260341504492359f, 0.18945061045506850f,
    0.18945061045506850f, 0.18260341504492359f, 0.16915651939500254f, 0.14959598881657673f,
    0.12462897125553387f, 0.09515851168249278f, 0.06225352393864789f, 0.02715245941175409f };

__device__ __forceinline__ float shfl16(float v, int s) {
    return __shfl_sync(0xffffffffu, v, s, 16);
}
__device__ __forceinline__ int deg25(int l) {
    return (l < 1) ? 0 : ((l < 4) ? 1 : ((l < 9) ? 2 : ((l < 16) ? 3 : 4)));
}
__device__ __forceinline__ float factf(int n) {
    float r = 1.f;
    for (int i = 2; i <= n; i++) r *= (float)i;
    return r;
}
__device__ __forceinline__ int warp_excl_scan(int v) {
    int x = v;
#pragma unroll
    for (int d = 1; d < 32; d <<= 1) {
        int y = __shfl_up_sync(0xffffffffu, x, d);
        if ((int)(threadIdx.x & 31) >= d) x += y;
    }
    return x - v;
}

template <int LM>
__device__ __forceinline__ void rsph(float x, float y, float z, float* out) {
    float phi = atan2f(y, x);
    float ct = fminf(fmaxf(z, -1.f), 1.f);
    float st = sqrtf(fmaxf(1.f - ct * ct, 0.f));
    float P[LM + 1][LM + 1];
    P[0][0] = 1.f;
#pragma unroll
    for (int m = 1; m <= LM; m++) P[m][m] = -(2.f * m - 1.f) * st * P[m - 1][m - 1];
#pragma unroll
    for (int m = 0; m < LM; m++) P[m + 1][m] = (2.f * m + 1.f) * ct * P[m][m];
#pragma unroll
    for (int m = 0; m <= LM; m++) {
#pragma unroll
        for (int l = m + 2; l <= LM; l++)
            P[l][m] = ((2.f * l - 1.f) * ct * P[l - 1][m] - (float)(l + m - 1) * P[l - 2][m]) / (float)(l - m);
    }
    int idx = 0;
#pragma unroll
    for (int l = 0; l <= LM; l++) {
#pragma unroll
        for (int mm = -l; mm <= l; mm++) {
            int ma = mm < 0 ? -mm : mm;
            float Nn = sqrtf((2.f * l + 1.f) / (4.f * PI_F) * factf(l - ma) / factf(l + ma));
            float cs = (ma & 1) ? -1.f : 1.f;
            float Yv;
            if (mm == 0)      Yv = Nn * P[l][0];
            else if (mm > 0)  Yv = 1.41421356237309515f * Nn * cs * cosf((float)mm * phi) * P[l][ma];
            else              Yv = 1.41421356237309515f * Nn * cs * sinf((float)ma * phi) * P[l][ma];
            out[idx++] = Yv;
        }
    }
}

// ---------- setup kernels ----------
__global__ void k_quad_Y() {
    int t = blockIdx.x * blockDim.x + threadIdx.x;
    if (t < 512) {
        int it = t >> 5, ip = t & 31;
        float ct = GLX[it];
        float ph = (float)ip * (2.f * PI_F / 32.f);
        float st = sqrtf(fmaxf(1.f - ct * ct, 0.f));
        float Yv[25];
        rsph<4>(st * cosf(ph), st * sinf(ph), ct, Yv);
#pragma unroll
        for (int i = 0; i < 25; i++) g_Y[t * 25 + i] = Yv[i];
        g_w[t] = GLW[it] * (2.f * PI_F / 32.f);
    } else if (t < 512 + 4096) {
        g_cnt[t - 512] = 0;
    }
}

__global__ void k_quad_G() {
    int t = blockIdx.x * blockDim.x + threadIdx.x;
    if (t >= 5625) return;
    int i = t / 225, rem = t % 225;
    int j = rem / 25, k = rem % 25;
    float acc = 0.f;
#pragma unroll 4
    for (int g = 0; g < 512; g++)
        acc += g_w[g] * g_Y[g * 25 + i] * g_Y[g * 25 + j] * g_Y[g * 25 + k];
    g_G[t] = (fabsf(acc) < 1e-6f) ? 0.f : acc;
}

__global__ void k_build_lists() {
    __shared__ float sG[5625];
    int tid = threadIdx.x;
    for (int t = tid; t < 5625; t += 256) sG[t] = g_G[t];
    __syncthreads();
    if (tid >= 32) return;
    int lane = tid;
    int cntH = 0, cntJ = 0;
    if (lane < 25) {
        for (int i = 0; i < 25; i++) {
            int c = 0;
            for (int j = 0; j < 9; j++) if (sG[i * 225 + j * 25 + lane] != 0.f) c++;
            if (c) { cntH++; cntJ += c; }
        }
    }
    int offH = warp_excl_scan(cntH);
    int offJ = warp_excl_scan(cntJ);
    if (lane < 25) g_hk[lane] = offH;
    if (lane == 24) g_hk[25] = offH + cntH;
    if (lane < 25) {
        int ho = offH, jo = offJ;
        for (int i = 0; i < 25; i++) {
            int c = 0;
            for (int j = 0; j < 9; j++) if (sG[i * 225 + j * 25 + lane] != 0.f) c++;
            if (c) {
                g_hi[ho] = i;
                g_hjs[ho] = jo;
                for (int j = 0; j < 9; j++) {
                    float v = sG[i * 225 + j * 25 + lane];
                    if (v != 0.f) { g_lj[jo] = j; g_lv[jo] = v; jo++; }
                }
                ho++;
            }
        }
        if (lane == 24) g_hjs[ho] = jo;
    }
    // entry-balanced quartile splits over k
    {
        int nHtot = __shfl_sync(0xffffffffu, offH + cntH, 24);
        int splits[5];
        splits[0] = 0; splits[4] = 25;
        for (int q = 1; q <= 3; q++) {
            int target = (q * nHtot) / 4;
            int best = q * 6, bd = 0x7fffffff;
            for (int k = 1; k < 25; k++) {
                int hkk = __shfl_sync(0xffffffffu, offH, k);
                int d = hkk - target; if (d < 0) d = -d;
                if (d < bd) { bd = d; best = k; }
            }
            splits[q] = best;
        }
        for (int q = 1; q <= 3; q++) if (splits[q] < splits[q - 1]) splits[q] = splits[q - 1];
        if (lane == 0) {
            for (int q = 0; q < 5; q++) g_ks4[q] = splits[q];
        }
    }
    int cntT = 0;
    if (lane < 9) {
        for (int i = 0; i < 9; i++)
            for (int j = 0; j < 9; j++)
                if (sG[i * 225 + j * 25 + lane] != 0.f) cntT++;
    }
    int offT = warp_excl_scan(cntT);
    if (lane < 9) g_tds[lane] = offT;
    if (lane == 8) g_tds[9] = offT + cntT;
    if (lane < 9) {
        int o = offT;
        for (int i = 0; i < 9; i++)
            for (int j = 0; j < 9; j++) {
                float v = sG[i * 225 + j * 25 + lane];
                if (v != 0.f) {
                    int di = (i < 1) ? 0 : (i < 4) ? 1 : 2;
                    int dj = (j < 1) ? 0 : (j < 4) ? 1 : 2;
                    g_tdp[o] = (di * 3 + dj) | (i << 8) | (j << 16);
                    g_tdv[o] = v;
                    o++;
                }
            }
    }
}

// ---------- CSR build ----------
__global__ void k_hist(const int* __restrict__ nbr) {
    int p = blockIdx.x * blockDim.x + threadIdx.x;
    if (p < NP) atomicAdd(&g_cnt[nbr[2 * p]], 1);
}
__global__ void k_scan() {
    __shared__ int s[1024];
    int t = threadIdx.x;
    int c[4], tot = 0;
#pragma unroll
    for (int i = 0; i < 4; i++) { c[i] = g_cnt[t * 4 + i]; tot += c[i]; }
    s[t] = tot; __syncthreads();
    for (int off = 1; off < 1024; off <<= 1) {
        int v = (t >= off) ? s[t - off] : 0;
        __syncthreads();
        s[t] += v;
        __syncthreads();
    }
    int base = s[t] - tot;
#pragma unroll
    for (int i = 0; i < 4; i++) {
        g_rowstart[t * 4 + i] = base;
        g_fillptr[t * 4 + i] = base;
        base += c[i];
    }
    if (t == 1023) g_rowstart[4096] = base;
}
__global__ void k_fill(const int* __restrict__ nbr) {
    int p = blockIdx.x * blockDim.x + threadIdx.x;
    if (p >= NP) return;
    int pos = atomicAdd(&g_fillptr[nbr[2 * p]], 1);
    g_plist[pos] = p;
    g_dstpos[p] = pos;
}

// ---------- pair tensor-product message pass (writes at CSR position) ----------
__global__ void k_pair_td(const int* __restrict__ nbr, const float* __restrict__ disp,
                          const int* __restrict__ Z, const float* __restrict__ W_rad,
                          const float* __restrict__ W1, const float* __restrict__ W2,
                          const float* __restrict__ W3) {
    __shared__ float sW1[768], sW2[768], sW3[768];
    __shared__ float sC[16][81];
    __shared__ float sSh[16][9];
    __shared__ int   sTds[10];
    __shared__ int   sTdp[768];
    __shared__ float sTdv[768];
    int tid = threadIdx.x;
    for (int t = tid; t < 768; t += 256) { sW1[t] = W1[t]; sW2[t] = W2[t]; sW3[t] = W3[t]; }
    if (tid < 10) sTds[tid] = g_tds[tid];
    int nT = g_tds[9];
    for (int t = tid; t < nT; t += 256) { sTdp[t] = g_tdp[t]; sTdv[t] = g_tdv[t]; }
    int pl = tid >> 4, lane = tid & 15;
    int p = blockIdx.x * 16 + pl;
    int src = nbr[2 * p + 1];
    int pos = g_dstpos[p];
    float dx = disp[3 * p], dy = disp[3 * p + 1], dz = disp[3 * p + 2];
    float r = sqrtf(dx * dx + dy * dy + dz * dz);
    float inv = 1.f / fmaxf(r, 1e-9f);
    float sh[9];
    rsph<2>(dx * inv, dy * inv, dz * inv, sh);
    if (lane == 0) {
#pragma unroll
        for (int i = 0; i < 9; i++) { sSh[pl][i] = sh[i]; g_sh[pos * 9 + i] = sh[i]; }
    }
    float xk = (float)(lane + 1) * r * (1.f / RCUT);
    float px = PI_F * xk;
    float rb = (px > 0.f) ? (sinf(px) / px) : 1.f;
    if (r >= RCUT) rb = 0.f;
    g_rb[pos * 16 + lane] = rb;
    __syncthreads();
    float y0 = 0.f;
    const float* wr = W_rad + Z[src] * 256;
#pragma unroll
    for (int k2 = 0; k2 < 16; k2++) y0 += shfl16(rb, k2) * wr[k2 * 16 + lane];
    float A0 = 0, A1 = 0, A2 = 0, B0 = 0, B1 = 0, B2 = 0;
#pragma unroll
    for (int f = 0; f < 16; f++) {
        float yv = shfl16(y0, f);
        A0 += yv * sW1[0 * 256 + f * 16 + lane];
        A1 += yv * sW1[1 * 256 + f * 16 + lane];
        A2 += yv * sW1[2 * 256 + f * 16 + lane];
        B0 += yv * sW2[0 * 256 + f * 16 + lane];
        B1 += yv * sW2[1 * 256 + f * 16 + lane];
        B2 += yv * sW2[2 * 256 + f * 16 + lane];
    }
    float P9[9];
    P9[0] = A0 * B0; P9[1] = A0 * B1; P9[2] = A0 * B2;
    P9[3] = A1 * B0; P9[4] = A1 * B1; P9[5] = A1 * B2;
    P9[6] = A2 * B0; P9[7] = A2 * B1; P9[8] = A2 * B2;
    for (int t = lane; t < 81; t += 16) sC[pl][t] = 0.f;
    __syncwarp(0xffffffffu);
    if (lane < 9) {
        int e0 = sTds[lane], e1 = sTds[lane + 1];
        for (int e = e0; e < e1; e++) {
            int pk = sTdp[e];
            sC[pl][lane * 9 + (pk & 255)] += sTdv[e] * sSh[pl][(pk >> 8) & 255] * sSh[pl][pk >> 16];
        }
    }
    __syncwarp(0xffffffffu);
    float tp[9];
#pragma unroll
    for (int k = 0; k < 9; k++) {
        float acc = 0.f;
#pragma unroll
        for (int dd = 0; dd < 9; dd++) acc += sC[pl][k * 9 + dd] * P9[dd];
        tp[k] = acc;
    }
#pragma unroll
    for (int k = 0; k < 9; k++) {
        int dk = (k < 1) ? 0 : (k < 4) ? 1 : 2;
        float acc = 0.f;
#pragma unroll
        for (int f = 0; f < 16; f++)
            acc += shfl16(tp[k], f) * sW3[dk * 256 + f * 16 + lane];
        g_pairy[pos * 144 + k * 16 + lane] = acc;
    }
}

// ---------- per-atom mean (contiguous CSR rows) ----------
__global__ void k_mp_gather() {
    int tid = threadIdx.x, a = blockIdx.x;
    int b0 = g_rowstart[a], deg = g_rowstart[a + 1] - b0;
    float a0 = 0.f, a1 = 0.f;
    for (int i = 0; i < deg; i++) {
        const float* py = g_pairy + (size_t)(b0 + i) * 144;
        a0 += py[tid];
        if (tid < 16) a1 += py[tid + 128];
    }
    float inv = 1.f / fmaxf((float)deg, 1.f);
    g_x0[a * 400 + tid] = a0 * inv;
    g_x0[a * 400 + 128 + tid] = (tid < 16) ? a1 * inv : 0.f;
    g_x0[a * 400 + 256 + tid] = 0.f;
    if (tid < 16) g_x0[a * 400 + 384 + tid] = 0.f;
}

// ---------- per-atom q/k/v projections ----------
__global__ void k_qkv(const float* __restrict__ x, const float* __restrict__ Wq,
                      const float* __restrict__ Wk, const float* __restrict__ Wv) {
    __shared__ float sq[1280], sk[1280], sv[1280];
    int tid = threadIdx.x;
    for (int t = tid; t < 1280; t += 256) { sq[t] = Wq[t]; sk[t] = Wk[t]; sv[t] = Wv[t]; }
    __syncthreads();
    int unit = tid >> 4, lane = tid & 15;
    for (int g = 0; g < 8; g++) {
        int gu = blockIdx.x * 128 + g * 16 + unit;
        int row = gu % 25;
        int d = deg25(row);
        float xv = x[gu * 16 + lane];
        float aq = 0, ak = 0, av = 0;
#pragma unroll
        for (int f = 0; f < 16; f++) {
            float xs = shfl16(xv, f);
            aq += xs * sq[d * 256 + f * 16 + lane];
            ak += xs * sk[d * 256 + f * 16 + lane];
            av += xs * sv[d * 256 + f * 16 + lane];
        }
        g_xq[gu * 16 + lane] = aq;
        g_xk[gu * 16 + lane] = ak;
        g_xv[gu * 16 + lane] = av;
    }
}

// ---------- attention pair kernel: 8 pairs x 32 threads, 2 features/lane, 4 k-quarters ----------
__global__ void __launch_bounds__(256) k_pair_att(const int* __restrict__ nbr,
                                                  const float* __restrict__ Wb) {
    __shared__ float  sH[8][640];
    __shared__ float4 sKV[8][25][8];   // {k_f0, k_f1, v_f0, v_f1}
    __shared__ float  sSh[8][12];
    __shared__ int    sHk[26];
    __shared__ unsigned char sHi8[640];
    __shared__ int    sKs[5];
    int tid = threadIdx.x;
    int pl = tid >> 5;           // pair (one warp per pair)
    int l32 = tid & 31;
    int l8 = tid & 7;            // feature pair: features 2*l8, 2*l8+1
    int q4 = (tid >> 3) & 3;     // k quarter
    if (tid < 26) sHk[tid] = g_hk[tid];
    if (tid < 5) sKs[tid] = g_ks4[tid];
    int nH = g_hk[25];
    for (int t = tid; t < nH; t += 256) sHi8[t] = (unsigned char)g_hi[t];
    int idx = blockIdx.x * 8 + pl;
    int p = g_plist[idx];
    int dst = nbr[2 * p], src = nbr[2 * p + 1];
    if (l32 < 9) sSh[pl][l32] = g_sh[idx * 9 + l32];
    float rbv = (l32 < 16) ? g_rb[idx * 16 + l32] : 0.f;
    // stage KV interleaved as float4 per (i, feature-pair)
    for (int t = l32; t < 200; t += 32) {
        int i = t >> 3, l = t & 7;
        float2 kk = *(const float2*)&g_xk[src * 400 + i * 16 + 2 * l];
        float2 vv = *(const float2*)&g_xv[src * 400 + i * 16 + 2 * l];
        sKV[pl][i][l] = make_float4(kk.x, kk.y, vv.x, vv.y);
    }
    __syncthreads();
    // per-pair H values (warp cooperates)
    for (int e = l32; e < nH; e += 32) {
        int j0 = g_hjs[e], j1 = g_hjs[e + 1];
        float acc = 0.f;
        for (int jj = j0; jj < j1; jj++) acc += g_lv[jj] * sSh[pl][g_lj[jj]];
        sH[pl][e] = acc;
    }
    // wf for this lane's 2 features (rb via warp shuffle, Wb via L1)
    float wf0 = 0.f, wf1 = 0.f;
#pragma unroll
    for (int k2 = 0; k2 < 16; k2++) {
        float rv = __shfl_sync(0xffffffffu, rbv, k2, 32);
        wf0 += rv * Wb[k2 * 16 + 2 * l8];
        wf1 += rv * Wb[k2 * 16 + 2 * l8 + 1];
    }
    __syncwarp(0xffffffffu);
    int k0 = sKs[q4], k1 = sKs[q4 + 1];
    float s0 = 0.f, s1 = 0.f;
    const float* qrow = g_xq + dst * 400;
    float* vrow = g_vf + (size_t)idx * 400;
    for (int k = k0; k < k1; k++) {
        int e0 = sHk[k], e1 = sHk[k + 1];
        float ak0 = 0.f, ak1 = 0.f, av0 = 0.f, av1 = 0.f;
        for (int e = e0; e < e1; e++) {
            float hv = sH[pl][e];
            float4 kv = sKV[pl][sHi8[e]][l8];
            ak0 += hv * kv.x; ak1 += hv * kv.y;
            av0 += hv * kv.z; av1 += hv * kv.w;
        }
        float2 q = *(const float2*)&qrow[k * 16 + 2 * l8];
        s0 += q.x * ak0; s1 += q.y * ak1;
        *(float2*)&vrow[k * 16 + 2 * l8] = make_float2(wf0 * av0, wf1 * av1);
    }
    float s = wf0 * s0 + wf1 * s1;
#pragma unroll
    for (int d = 16; d >= 1; d >>= 1)
        s += __shfl_down_sync(0xffffffffu, s, d, 32);
    if (l32 == 0) g_sv[idx] = s * 0.05f;
}

// ---------- fused softmax + aggregation + output projection (contiguous CSR) ----------
__global__ void __launch_bounds__(128) k_att_out(const float* __restrict__ Wo,
                                                 const float* __restrict__ bo,
                                                 float* __restrict__ xout) {
    __shared__ float sWo[1280];
    __shared__ float sb[16];
    __shared__ float sAgg[400];
    __shared__ float red[128];
    int tid = threadIdx.x, a = blockIdx.x;
    for (int t = tid; t < 1280; t += 128) sWo[t] = Wo[t];
    if (tid < 16) sb[tid] = bo[tid];
    int b0 = g_rowstart[a], deg = g_rowstart[a + 1] - b0;
    float m = -1e30f;
    for (int i = tid; i < deg; i += 128) m = fmaxf(m, g_sv[b0 + i]);
    red[tid] = m; __syncthreads();
    for (int s = 64; s > 0; s >>= 1) { if (tid < s) red[tid] = fmaxf(red[tid], red[tid + s]); __syncthreads(); }
    m = red[0]; __syncthreads();
    float d = 0.f;
    for (int i = tid; i < deg; i += 128) d += expf(g_sv[b0 + i] - m);
    red[tid] = d; __syncthreads();
    for (int s = 64; s > 0; s >>= 1) { if (tid < s) red[tid] += red[tid + s]; __syncthreads(); }
    float invden = 1.f / (red[0] + 1e-9f);
    __syncthreads();
    if (tid < 100) {
        float4 acc0 = make_float4(0.f, 0.f, 0.f, 0.f);
        float4 acc1 = make_float4(0.f, 0.f, 0.f, 0.f);
        int i = 0;
        for (; i + 1 < deg; i += 2) {
            float al0 = expf(g_sv[b0 + i] - m) * invden;
            float al1 = expf(g_sv[b0 + i + 1] - m) * invden;
            float4 v0 = *(const float4*)(g_vf + (size_t)(b0 + i) * 400 + tid * 4);
            float4 v1 = *(const float4*)(g_vf + (size_t)(b0 + i + 1) * 400 + tid * 4);
            acc0.x += al0 * v0.x; acc0.y += al0 * v0.y; acc0.z += al0 * v0.z; acc0.w += al0 * v0.w;
            acc1.x += al1 * v1.x; acc1.y += al1 * v1.y; acc1.z += al1 * v1.z; acc1.w += al1 * v1.w;
        }
        if (i < deg) {
            float al = expf(g_sv[b0 + i] - m) * invden;
            float4 vv = *(const float4*)(g_vf + (size_t)(b0 + i) * 400 + tid * 4);
            acc0.x += al * vv.x; acc0.y += al * vv.y; acc0.z += al * vv.z; acc0.w += al * vv.w;
        }
        acc0.x += acc1.x; acc0.y += acc1.y; acc0.z += acc1.z; acc0.w += acc1.w;
        *(float4*)&sAgg[tid * 4] = acc0;
    }
    __syncthreads();
    for (int idx = tid; idx < 400; idx += 128) {
        int row = idx >> 4, g = idx & 15, dg = deg25(row);
        const float* w = &sWo[dg * 256];
        float acc = 0.f;
#pragma unroll
        for (int f = 0; f < 16; f++) acc += sAgg[row * 16 + f] * w[f * 16 + g];
        if (row == 0) acc += sb[g];
        xout[a * 400 + idx] = acc;
    }
}

// ---------- final residual on row 0 ----------
__global__ void k_final(const int* __restrict__ Z, const float* __restrict__ emb,
                        const float* __restrict__ W_emb, const float* __restrict__ b_emb,
                        float* __restrict__ out) {
    int tid = blockIdx.x * blockDim.x + threadIdx.x;
    int atom = tid >> 4, lane = tid & 15;
    if (atom >= NA) return;
    const float* er = emb + Z[atom] * 32;
    float acc = b_emb[lane];
#pragma unroll 8
    for (int e = 0; e < 32; e++) acc += er[e] * W_emb[e * 16 + lane];
    out[atom * 400 + lane] += acc;
}

extern "C" void kernel_launch(void* const* d_in, const int* in_sizes, int n_in,
                              void* d_out, int out_size) {
    const int*   Z     = (const int*)d_in[0];
    const int*   nbr   = (const int*)d_in[1];
    const float* disp  = (const float*)d_in[2];
    const float* W_rad = (const float*)d_in[3];
    const float* emb   = (const float*)d_in[4];
    const float* W_emb = (const float*)d_in[5];
    const float* b_emb = (const float*)d_in[6];
    const float* tdW1  = (const float*)d_in[7];
    const float* tdW2  = (const float*)d_in[8];
    const float* tdW3  = (const float*)d_in[9];
    const float* Wb[2] = { (const float*)d_in[10], (const float*)d_in[16] };
    const float* Wq[2] = { (const float*)d_in[11], (const float*)d_in[17] };
    const float* Wk[2] = { (const float*)d_in[12], (const float*)d_in[18] };
    const float* Wv[2] = { (const float*)d_in[13], (const float*)d_in[19] };
    const float* Wo[2] = { (const float*)d_in[14], (const float*)d_in[20] };
    const float* bo[2] = { (const float*)d_in[15], (const float*)d_in[21] };
    float* out = (float*)d_out;

    float *x0p, *x1p;
    cudaGetSymbolAddress((void**)&x0p, g_x0);
    cudaGetSymbolAddress((void**)&x1p, g_x1);

    k_quad_Y<<<18, 256>>>();
    k_quad_G<<<45, 128>>>();
    k_build_lists<<<1, 256>>>();
    k_hist<<<NP / 256, 256>>>(nbr);
    k_scan<<<1, 1024>>>();
    k_fill<<<NP / 256, 256>>>(nbr);
    k_pair_td<<<NP / 16, 256>>>(nbr, disp, Z, W_rad, tdW1, tdW2, tdW3);
    k_mp_gather<<<NA, 128>>>();

    for (int L = 0; L < 2; L++) {
        const float* xi = (L == 0) ? x0p : x1p;
        float* xo = (L == 0) ? x1p : out;
        k_qkv<<<NA * 25 / 128, 256>>>(xi, Wq[L], Wk[L], Wv[L]);
        k_pair_att<<<NP / 8, 256>>>(nbr, Wb[L]);
        k_att_out<<<NA, 128>>>(Wo[L], bo[L], xo);
    }
    k_final<<<256, 256>>>(Z, emb, W_emb, b_emb, out);
}

// round 16
// speedup vs baseline: 1.1827x; 1.0930x over previous
#include <cuda_runtime.h>
#include <math.h>

#define PI_F 3.14159265358979323846f

static constexpr int NA = 4096;
static constexpr int NP = 49152;
static constexpr float RCUT = 5.0f;

// ---------- setup tables ----------
__device__ float g_Y[512 * 25];
__device__ float g_w[512];
__device__ float g_Gp[4][5625];
__device__ float g_G[5625];
__device__ int   g_hk[26];
__device__ int   g_hi[640];
__device__ int   g_hjs[648];
__device__ int   g_lj[5664];
__device__ float g_lv[5664];
__device__ int   g_tds[10];
__device__ int   g_tdp[768];
__device__ float g_tdv[768];
__device__ int   g_ks4[5];

// ---------- CSR by destination atom ----------
__device__ int g_cnt[4096];
__device__ int g_rowstart[4097];
__device__ int g_fillptr[4096];
__device__ int g_plist[NP];
__device__ int g_dstpos[NP];

// ---------- per-pair / per-atom data (pair arrays in CSR order) ----------
__device__ float g_sh[NP * 9];
__device__ float g_rb[NP * 16];
__device__ float g_pairy[NP * 144];
__device__ float g_x0[NA * 400];
__device__ float g_x1[NA * 400];
__device__ float g_xq[NA * 400];
__device__ float g_xk[NA * 400];
__device__ float g_xv[NA * 400];
__device__ float g_vf[(size_t)NP * 400];
__device__ float g_sv[NP];

__constant__ float GLX[16] = {
    -0.98940093499164993f, -0.94457502307323258f, -0.86563120238783174f, -0.75540440835500303f,
    -0.61787624440264375f, -0.45801677765722739f, -0.28160355077925891f, -0.09501250983763744f,
     0.09501250983763744f,  0.28160355077925891f,  0.45801677765722739f,  0.61787624440264375f,
     0.75540440835500303f,  0.86563120238783174f,  0.94457502307323258f,  0.98940093499164993f };
__constant__ float GLW[16] = {
    0.02715245941175409f, 0.06225352393864789f, 0.09515851168249278f, 0.12462897125553387f,
    0.14959598881657673f, 0.16915651939500254f, 0.18260341504492359f, 0.18945061045506850f,
    0.18945061045506850f, 0.18260341504492359f, 0.16915651939500254f, 0.14959598881657673f,
    0.12462897125553387f, 0.09515851168249278f, 0.06225352393864789f, 0.02715245941175409f };

__device__ __forceinline__ float shfl16(float v, int s) {
    return __shfl_sync(0xffffffffu, v, s, 16);
}
__device__ __forceinline__ int deg25(int l) {
    return (l < 1) ? 0 : ((l < 4) ? 1 : ((l < 9) ? 2 : ((l < 16) ? 3 : 4)));
}
__device__ __forceinline__ float factf(int n) {
    float r = 1.f;
    for (int i = 2; i <= n; i++) r *= (float)i;
    return r;
}
__device__ __forceinline__ int warp_excl_scan(int v) {
    int x = v;
#pragma unroll
    for (int d = 1; d < 32; d <<= 1) {
        int y = __shfl_up_sync(0xffffffffu, x, d);
        if ((int)(threadIdx.x & 31) >= d) x += y;
    }
    return x - v;
}

template <int LM>
__device__ __forceinline__ void rsph(float x, float y, float z, float* out) {
    float phi = atan2f(y, x);
    float ct = fminf(fmaxf(z, -1.f), 1.f);
    float st = sqrtf(fmaxf(1.f - ct * ct, 0.f));
    float P[LM + 1][LM + 1];
    P[0][0] = 1.f;
#pragma unroll
    for (int m = 1; m <= LM; m++) P[m][m] = -(2.f * m - 1.f) * st * P[m - 1][m - 1];
#pragma unroll
    for (int m = 0; m < LM; m++) P[m + 1][m] = (2.f * m + 1.f) * ct * P[m][m];
#pragma unroll
    for (int m = 0; m <= LM; m++) {
#pragma unroll
        for (int l = m + 2; l <= LM; l++)
            P[l][m] = ((2.f * l - 1.f) * ct * P[l - 1][m] - (float)(l + m - 1) * P[l - 2][m]) / (float)(l - m);
    }
    int idx = 0;
#pragma unroll
    for (int l = 0; l <= LM; l++) {
#pragma unroll
        for (int mm = -l; mm <= l; mm++) {
            int ma = mm < 0 ? -mm : mm;
            float Nn = sqrtf((2.f * l + 1.f) / (4.f * PI_F) * factf(l - ma) / factf(l + ma));
            float cs = (ma & 1) ? -1.f : 1.f;
            float Yv;
            if (mm == 0)      Yv = Nn * P[l][0];
            else if (mm > 0)  Yv = 1.41421356237309515f * Nn * cs * cosf((float)mm * phi) * P[l][ma];
            else              Yv = 1.41421356237309515f * Nn * cs * sinf((float)ma * phi) * P[l][ma];
            out[idx++] = Yv;
        }
    }
}

// closed-form real SH for l<=2 (matches reference recurrence to fp rounding)
__device__ __forceinline__ void sh9(float x, float y, float z, float* sh) {
    sh[0] = 0.28209479177387814f;
    sh[1] = 0.4886025119029199f * y;
    sh[2] = 0.4886025119029199f * z;
    sh[3] = 0.4886025119029199f * x;
    sh[4] = 1.0925484305920792f * x * y;
    sh[5] = 1.0925484305920792f * y * z;
    sh[6] = 0.31539156525252005f * (3.f * z * z - 1.f);
    sh[7] = 1.0925484305920792f * x * z;
    sh[8] = 0.5462742152960396f * (x * x - y * y);
}

// ---------- setup kernels ----------
__global__ void k_quad_Y() {
    int t = blockIdx.x * blockDim.x + threadIdx.x;
    if (t < 512) {
        int it = t >> 5, ip = t & 31;
        float ct = GLX[it];
        float ph = (float)ip * (2.f * PI_F / 32.f);
        float st = sqrtf(fmaxf(1.f - ct * ct, 0.f));
        float Yv[25];
        rsph<4>(st * cosf(ph), st * sinf(ph), ct, Yv);
#pragma unroll
        for (int i = 0; i < 25; i++) g_Y[t * 25 + i] = Yv[i];
        g_w[t] = GLW[it] * (2.f * PI_F / 32.f);
    } else if (t < 512 + 4096) {
        g_cnt[t - 512] = 0;
    }
}

__global__ void k_quad_Gp() {
    int t = blockIdx.x * blockDim.x + threadIdx.x;
    if (t >= 22500) return;
    int s = t / 5625, cell = t % 5625;
    int i = cell / 225, rem = cell % 225;
    int j = rem / 25, k = rem % 25;
    float acc = 0.f;
    int g0 = s * 128, g1 = g0 + 128;
#pragma unroll 4
    for (int g = g0; g < g1; g++)
        acc += g_w[g] * g_Y[g * 25 + i] * g_Y[g * 25 + j] * g_Y[g * 25 + k];
    g_Gp[s][cell] = acc;
}
__global__ void k_quad_Gsum() {
    int t = blockIdx.x * blockDim.x + threadIdx.x;
    if (t >= 5625) return;
    float acc = g_Gp[0][t] + g_Gp[1][t] + g_Gp[2][t] + g_Gp[3][t];
    g_G[t] = (fabsf(acc) < 1e-6f) ? 0.f : acc;
}

__global__ void k_build_lists() {
    __shared__ float sG[5625];
    int tid = threadIdx.x;
    for (int t = tid; t < 5625; t += 256) sG[t] = g_G[t];
    __syncthreads();
    if (tid >= 32) return;
    int lane = tid;
    int cntH = 0, cntJ = 0;
    if (lane < 25) {
        for (int i = 0; i < 25; i++) {
            int c = 0;
            for (int j = 0; j < 9; j++) if (sG[i * 225 + j * 25 + lane] != 0.f) c++;
            if (c) { cntH++; cntJ += c; }
        }
    }
    int offH = warp_excl_scan(cntH);
    int offJ = warp_excl_scan(cntJ);
    if (lane < 25) g_hk[lane] = offH;
    if (lane == 24) g_hk[25] = offH + cntH;
    if (lane < 25) {
        int ho = offH, jo = offJ;
        for (int i = 0; i < 25; i++) {
            int c = 0;
            for (int j = 0; j < 9; j++) if (sG[i * 225 + j * 25 + lane] != 0.f) c++;
            if (c) {
                g_hi[ho] = i;
                g_hjs[ho] = jo;
                for (int j = 0; j < 9; j++) {
                    float v = sG[i * 225 + j * 25 + lane];
                    if (v != 0.f) { g_lj[jo] = j; g_lv[jo] = v; jo++; }
                }
                ho++;
            }
        }
        if (lane == 24) g_hjs[ho] = jo;
    }
    {
        int nHtot = __shfl_sync(0xffffffffu, offH + cntH, 24);
        int splits[5];
        splits[0] = 0; splits[4] = 25;
        for (int q = 1; q <= 3; q++) {
            int target = (q * nHtot) / 4;
            int best = q * 6, bd = 0x7fffffff;
            for (int k = 1; k < 25; k++) {
                int hkk = __shfl_sync(0xffffffffu, offH, k);
                int d = hkk - target; if (d < 0) d = -d;
                if (d < bd) { bd = d; best = k; }
            }
            splits[q] = best;
        }
        for (int q = 1; q <= 3; q++) if (splits[q] < splits[q - 1]) splits[q] = splits[q - 1];
        if (lane == 0) {
            for (int q = 0; q < 5; q++) g_ks4[q] = splits[q];
        }
    }
    int cntT = 0;
    if (lane < 9) {
        for (int i = 0; i < 9; i++)
            for (int j = 0; j < 9; j++)
                if (sG[i * 225 + j * 25 + lane] != 0.f) cntT++;
    }
    int offT = warp_excl_scan(cntT);
    if (lane < 9) g_tds[lane] = offT;
    if (lane == 8) g_tds[9] = offT + cntT;
    if (lane < 9) {
        int o = offT;
        for (int i = 0; i < 9; i++)
            for (int j = 0; j < 9; j++) {
                float v = sG[i * 225 + j * 25 + lane];
                if (v != 0.f) {
                    int di = (i < 1) ? 0 : (i < 4) ? 1 : 2;
                    int dj = (j < 1) ? 0 : (j < 4) ? 1 : 2;
                    g_tdp[o] = (di * 3 + dj) | (i << 8) | (j << 16);
                    g_tdv[o] = v;
                    o++;
                }
            }
    }
}

// ---------- CSR build ----------
__global__ void k_hist(const int* __restrict__ nbr) {
    int p = blockIdx.x * blockDim.x + threadIdx.x;
    if (p < NP) atomicAdd(&g_cnt[nbr[2 * p]], 1);
}
__global__ void k_scan() {
    __shared__ int s[1024];
    int t = threadIdx.x;
    int c[4], tot = 0;
#pragma unroll
    for (int i = 0; i < 4; i++) { c[i] = g_cnt[t * 4 + i]; tot += c[i]; }
    s[t] = tot; __syncthreads();
    for (int off = 1; off < 1024; off <<= 1) {
        int v = (t >= off) ? s[t - off] : 0;
        __syncthreads();
        s[t] += v;
        __syncthreads();
    }
    int base = s[t] - tot;
#pragma unroll
    for (int i = 0; i < 4; i++) {
        g_rowstart[t * 4 + i] = base;
        g_fillptr[t * 4 + i] = base;
        base += c[i];
    }
    if (t == 1023) g_rowstart[4096] = base;
}
__global__ void k_fill(const int* __restrict__ nbr) {
    int p = blockIdx.x * blockDim.x + threadIdx.x;
    if (p >= NP) return;
    int pos = atomicAdd(&g_fillptr[nbr[2 * p]], 1);
    g_plist[pos] = p;
    g_dstpos[p] = pos;
}

// ---------- pair tensor-product message pass (writes at CSR position) ----------
__global__ void k_pair_td(const int* __restrict__ nbr, const float* __restrict__ disp,
                          const int* __restrict__ Z, const float* __restrict__ W_rad,
                          const float* __restrict__ W1, const float* __restrict__ W2,
                          const float* __restrict__ W3) {
    __shared__ float sW1[768], sW2[768], sW3[768];
    __shared__ float sC[16][81];
    __shared__ float sSh[16][9];
    __shared__ int   sTds[10];
    __shared__ int   sTdp[768];
    __shared__ float sTdv[768];
    int tid = threadIdx.x;
    for (int t = tid; t < 768; t += 256) { sW1[t] = W1[t]; sW2[t] = W2[t]; sW3[t] = W3[t]; }
    if (tid < 10) sTds[tid] = g_tds[tid];
    int nT = g_tds[9];
    for (int t = tid; t < nT; t += 256) { sTdp[t] = g_tdp[t]; sTdv[t] = g_tdv[t]; }
    int pl = tid >> 4, lane = tid & 15;
    int p = blockIdx.x * 16 + pl;
    int src = nbr[2 * p + 1];
    int pos = g_dstpos[p];
    float dx = disp[3 * p], dy = disp[3 * p + 1], dz = disp[3 * p + 2];
    float r = sqrtf(dx * dx + dy * dy + dz * dz);
    float inv = 1.f / fmaxf(r, 1e-9f);
    float sh[9];
    sh9(dx * inv, dy * inv, dz * inv, sh);
    if (lane == 0) {
#pragma unroll
        for (int i = 0; i < 9; i++) { sSh[pl][i] = sh[i]; g_sh[pos * 9 + i] = sh[i]; }
    }
    float xk = (float)(lane + 1) * r * (1.f / RCUT);
    float px = PI_F * xk;
    float rb = (px > 0.f) ? (sinf(px) / px) : 1.f;
    if (r >= RCUT) rb = 0.f;
    g_rb[pos * 16 + lane] = rb;
    __syncthreads();
    float y0 = 0.f;
    const float* wr = W_rad + Z[src] * 256;
#pragma unroll
    for (int k2 = 0; k2 < 16; k2++) y0 += shfl16(rb, k2) * wr[k2 * 16 + lane];
    float A0 = 0, A1 = 0, A2 = 0, B0 = 0, B1 = 0, B2 = 0;
#pragma unroll
    for (int f = 0; f < 16; f++) {
        float yv = shfl16(y0, f);
        A0 += yv * sW1[0 * 256 + f * 16 + lane];
        A1 += yv * sW1[1 * 256 + f * 16 + lane];
        A2 += yv * sW1[2 * 256 + f * 16 + lane];
        B0 += yv * sW2[0 * 256 + f * 16 + lane];
        B1 += yv * sW2[1 * 256 + f * 16 + lane];
        B2 += yv * sW2[2 * 256 + f * 16 + lane];
    }
    float P9[9];
    P9[0] = A0 * B0; P9[1] = A0 * B1; P9[2] = A0 * B2;
    P9[3] = A1 * B0; P9[4] = A1 * B1; P9[5] = A1 * B2;
    P9[6] = A2 * B0; P9[7] = A2 * B1; P9[8] = A2 * B2;
    for (int t = lane; t < 81; t += 16) sC[pl][t] = 0.f;
    __syncwarp(0xffffffffu);
    if (lane < 9) {
        int e0 = sTds[lane], e1 = sTds[lane + 1];
        for (int e = e0; e < e1; e++) {
            int pk = sTdp[e];
            sC[pl][lane * 9 + (pk & 255)] += sTdv[e] * sSh[pl][(pk >> 8) & 255] * sSh[pl][pk >> 16];
        }
    }
    __syncwarp(0xffffffffu);
    float tp[9];
#pragma unroll
    for (int k = 0; k < 9; k++) {
        float acc = 0.f;
#pragma unroll
        for (int dd = 0; dd < 9; dd++) acc += sC[pl][k * 9 + dd] * P9[dd];
        tp[k] = acc;
    }
#pragma unroll
    for (int k = 0; k < 9; k++) {
        int dk = (k < 1) ? 0 : (k < 4) ? 1 : 2;
        float acc = 0.f;
#pragma unroll
        for (int f = 0; f < 16; f++)
            acc += shfl16(tp[k], f) * sW3[dk * 256 + f * 16 + lane];
        g_pairy[pos * 144 + k * 16 + lane] = acc;
    }
}

// ---------- per-atom mean (contiguous CSR rows) ----------
__global__ void k_mp_gather() {
    int tid = threadIdx.x, a = blockIdx.x;
    int b0 = g_rowstart[a], deg = g_rowstart[a + 1] - b0;
    float a0 = 0.f, a1 = 0.f;
    for (int i = 0; i < deg; i++) {
        const float* py = g_pairy + (size_t)(b0 + i) * 144;
        a0 += py[tid];
        if (tid < 16) a1 += py[tid + 128];
    }
    float inv = 1.f / fmaxf((float)deg, 1.f);
    g_x0[a * 400 + tid] = a0 * inv;
    g_x0[a * 400 + 128 + tid] = (tid < 16) ? a1 * inv : 0.f;
    g_x0[a * 400 + 256 + tid] = 0.f;
    if (tid < 16) g_x0[a * 400 + 384 + tid] = 0.f;
}

// ---------- per-atom q/k/v projections ----------
__global__ void k_qkv(const float* __restrict__ x, const float* __restrict__ Wq,
                      const float* __restrict__ Wk, const float* __restrict__ Wv) {
    __shared__ float sq[1280], sk[1280], sv[1280];
    int tid = threadIdx.x;
    for (int t = tid; t < 1280; t += 256) { sq[t] = Wq[t]; sk[t] = Wk[t]; sv[t] = Wv[t]; }
    __syncthreads();
    int unit = tid >> 4, lane = tid & 15;
    for (int g = 0; g < 8; g++) {
        int gu = blockIdx.x * 128 + g * 16 + unit;
        int row = gu % 25;
        int d = deg25(row);
        float xv = x[gu * 16 + lane];
        float aq = 0, ak = 0, av = 0;
#pragma unroll
        for (int f = 0; f < 16; f++) {
            float xs = shfl16(xv, f);
            aq += xs * sq[d * 256 + f * 16 + lane];
            ak += xs * sk[d * 256 + f * 16 + lane];
            av += xs * sv[d * 256 + f * 16 + lane];
        }
        g_xq[gu * 16 + lane] = aq;
        g_xk[gu * 16 + lane] = ak;
        g_xv[gu * 16 + lane] = av;
    }
}

// ---------- attention pair kernel: 8 pairs x 32 threads, 2 features/lane, 4 k-quarters ----------
__global__ void __launch_bounds__(256) k_pair_att(const int* __restrict__ nbr,
                                                  const float* __restrict__ Wb) {
    __shared__ float  sH[8][640];
    __shared__ float4 sKV[8][25][8];   // {k_f0, k_f1, v_f0, v_f1}
    __shared__ float  sSh[8][12];
    __shared__ int    sHk[26];
    __shared__ unsigned char sHi8[640];
    __shared__ int    sKs[5];
    int tid = threadIdx.x;
    int pl = tid >> 5;
    int l32 = tid & 31;
    int l8 = tid & 7;
    int q4 = (tid >> 3) & 3;
    if (tid < 26) sHk[tid] = g_hk[tid];
    if (tid < 5) sKs[tid] = g_ks4[tid];
    int nH = g_hk[25];
    for (int t = tid; t < nH; t += 256) sHi8[t] = (unsigned char)g_hi[t];
    int idx = blockIdx.x * 8 + pl;
    int p = g_plist[idx];
    int dst = nbr[2 * p], src = nbr[2 * p + 1];
    if (l32 < 9) sSh[pl][l32] = g_sh[idx * 9 + l32];
    float rbv = (l32 < 16) ? g_rb[idx * 16 + l32] : 0.f;
    for (int t = l32; t < 200; t += 32) {
        int i = t >> 3, l = t & 7;
        float2 kk = *(const float2*)&g_xk[src * 400 + i * 16 + 2 * l];
        float2 vv = *(const float2*)&g_xv[src * 400 + i * 16 + 2 * l];
        sKV[pl][i][l] = make_float4(kk.x, kk.y, vv.x, vv.y);
    }
    __syncthreads();
    for (int e = l32; e < nH; e += 32) {
        int j0 = g_hjs[e], j1 = g_hjs[e + 1];
        float acc = 0.f;
        for (int jj = j0; jj < j1; jj++) acc += g_lv[jj] * sSh[pl][g_lj[jj]];
        sH[pl][e] = acc;
    }
    float wf0 = 0.f, wf1 = 0.f;
#pragma unroll
    for (int k2 = 0; k2 < 16; k2++) {
        float rv = __shfl_sync(0xffffffffu, rbv, k2, 32);
        wf0 += rv * Wb[k2 * 16 + 2 * l8];
        wf1 += rv * Wb[k2 * 16 + 2 * l8 + 1];
    }
    __syncwarp(0xffffffffu);
    int k0 = sKs[q4], k1 = sKs[q4 + 1];
    float s0 = 0.f, s1 = 0.f;
    const float* qrow = g_xq + dst * 400;
    float* vrow = g_vf + (size_t)idx * 400;
    for (int k = k0; k < k1; k++) {
        int e0 = sHk[k], e1 = sHk[k + 1];
        float ak0 = 0.f, ak1 = 0.f, av0 = 0.f, av1 = 0.f;
        for (int e = e0; e < e1; e++) {
            float hv = sH[pl][e];
            float4 kv = sKV[pl][sHi8[e]][l8];
            ak0 += hv * kv.x; ak1 += hv * kv.y;
            av0 += hv * kv.z; av1 += hv * kv.w;
        }
        float2 q = *(const float2*)&qrow[k * 16 + 2 * l8];
        s0 += q.x * ak0; s1 += q.y * ak1;
        *(float2*)&vrow[k * 16 + 2 * l8] = make_float2(wf0 * av0, wf1 * av1);
    }
    float s = wf0 * s0 + wf1 * s1;
#pragma unroll
    for (int d = 16; d >= 1; d >>= 1)
        s += __shfl_down_sync(0xffffffffu, s, d, 32);
    if (l32 == 0) g_sv[idx] = s * 0.05f;
}

// ---------- fused softmax + aggregation + output projection (256 thr, deg split 2-way) ----------
__global__ void __launch_bounds__(256) k_att_out(const float* __restrict__ Wo,
                                                 const float* __restrict__ bo,
                                                 float* __restrict__ xout) {
    __shared__ float sWo[1280];
    __shared__ float sb[16];
    __shared__ float sAgg[2][400];
    __shared__ float red[256];
    int tid = threadIdx.x, a = blockIdx.x;
    for (int t = tid; t < 1280; t += 256) sWo[t] = Wo[t];
    if (tid < 16) sb[tid] = bo[tid];
    int b0 = g_rowstart[a], deg = g_rowstart[a + 1] - b0;
    float m = -1e30f;
    for (int i = tid; i < deg; i += 256) m = fmaxf(m, g_sv[b0 + i]);
    red[tid] = m; __syncthreads();
    for (int s = 128; s > 0; s >>= 1) { if (tid < s) red[tid] = fmaxf(red[tid], red[tid + s]); __syncthreads(); }
    m = red[0]; __syncthreads();
    float d = 0.f;
    for (int i = tid; i < deg; i += 256) d += expf(g_sv[b0 + i] - m);
    red[tid] = d; __syncthreads();
    for (int s = 128; s > 0; s >>= 1) { if (tid < s) red[tid] += red[tid + s]; __syncthreads(); }
    float invden = 1.f / (red[0] + 1e-9f);
    __syncthreads();
    int grp = tid >> 7, t128 = tid & 127;
    int half = (deg + 1) >> 1;
    int i0 = grp ? half : 0;
    int i1 = grp ? deg : half;
    if (t128 < 100) {
        float4 acc = make_float4(0.f, 0.f, 0.f, 0.f);
        for (int i = i0; i < i1; i++) {
            float al = expf(g_sv[b0 + i] - m) * invden;
            float4 vv = *(const float4*)(g_vf + (size_t)(b0 + i) * 400 + t128 * 4);
            acc.x += al * vv.x; acc.y += al * vv.y;
            acc.z += al * vv.z; acc.w += al * vv.w;
        }
        *(float4*)&sAgg[grp][t128 * 4] = acc;
    }
    __syncthreads();
    for (int t = tid; t < 400; t += 256) sAgg[0][t] += sAgg[1][t];
    __syncthreads();
    for (int idx = tid; idx < 400; idx += 256) {
        int row = idx >> 4, g = idx & 15, dg = deg25(row);
        const float* w = &sWo[dg * 256];
        float acc = 0.f;
#pragma unroll
        for (int f = 0; f < 16; f++) acc += sAgg[0][row * 16 + f] * w[f * 16 + g];
        if (row == 0) acc += sb[g];
        xout[a * 400 + idx] = acc;
    }
}

// ---------- final residual on row 0 ----------
__global__ void k_final(const int* __restrict__ Z, const float* __restrict__ emb,
                        const float* __restrict__ W_emb, const float* __restrict__ b_emb,
                        float* __restrict__ out) {
    int tid = blockIdx.x * blockDim.x + threadIdx.x;
    int atom = tid >> 4, lane = tid & 15;
    if (atom >= NA) return;
    const float* er = emb + Z[atom] * 32;
    float acc = b_emb[lane];
#pragma unroll 8
    for (int e = 0; e < 32; e++) acc += er[e] * W_emb[e * 16 + lane];
    out[atom * 400 + lane] += acc;
}

extern "C" void kernel_launch(void* const* d_in, const int* in_sizes, int n_in,
                              void* d_out, int out_size) {
    const int*   Z     = (const int*)d_in[0];
    const int*   nbr   = (const int*)d_in[1];
    const float* disp  = (const float*)d_in[2];
    const float* W_rad = (const float*)d_in[3];
    const float* emb   = (const float*)d_in[4];
    const float* W_emb = (const float*)d_in[5];
    const float* b_emb = (const float*)d_in[6];
    const float* tdW1  = (const float*)d_in[7];
    const float* tdW2  = (const float*)d_in[8];
    const float* tdW3  = (const float*)d_in[9];
    const float* Wb[2] = { (const float*)d_in[10], (const float*)d_in[16] };
    const float* Wq[2] = { (const float*)d_in[11], (const float*)d_in[17] };
    const float* Wk[2] = { (const float*)d_in[12], (const float*)d_in[18] };
    const float* Wv[2] = { (const float*)d_in[13], (const float*)d_in[19] };
    const float* Wo[2] = { (const float*)d_in[14], (const float*)d_in[20] };
    const float* bo[2] = { (const float*)d_in[15], (const float*)d_in[21] };
    float* out = (float*)d_out;

    float *x0p, *x1p;
    cudaGetSymbolAddress((void**)&x0p, g_x0);
    cudaGetSymbolAddress((void**)&x1p, g_x1);

    k_quad_Y<<<18, 256>>>();
    k_quad_Gp<<<88, 256>>>();
    k_quad_Gsum<<<23, 256>>>();
    k_build_lists<<<1, 256>>>();
    k_hist<<<NP / 256, 256>>>(nbr);
    k_scan<<<1, 1024>>>();
    k_fill<<<NP / 256, 256>>>(nbr);
    k_pair_td<<<NP / 16, 256>>>(nbr, disp, Z, W_rad, tdW1, tdW2, tdW3);
    k_mp_gather<<<NA, 128>>>();

    for (int L = 0; L < 2; L++) {
        const float* xi = (L == 0) ? x0p : x1p;
        float* xo = (L == 0) ? x1p : out;
        k_qkv<<<NA * 25 / 128, 256>>>(xi, Wq[L], Wk[L], Wv[L]);
        k_pair_att<<<NP / 8, 256>>>(nbr, Wb[L]);
        k_att_out<<<NA, 256>>>(Wo[L], bo[L], xo);
    }
    k_final<<<256, 256>>>(Z, emb, W_emb, b_emb, out);
}